// round 1
// baseline (speedup 1.0000x reference)
#include <cuda_runtime.h>

// HexEye: mean over 9x9 reflect-padded patches at 721 receptor centers,
// for 32 batches x 3 channels of a 600x800 fp32 image.
//
// Layout:
//   d_in[0]: stim        float32 [32, 3, 600, 800]
//   d_in[1]: receptor_x  int32   [721]
//   d_in[2]: receptor_y  int32   [721]
//   d_out  : float32 [32, 3, 721]
//
// One warp per output element. Lane l covers patch elements {l, l+32, l+64}
// (81 total). Consecutive lanes read consecutive x -> coalesced row fetches.

#define HEX_H    600
#define HEX_W    800
#define HEX_K    9
#define HEX_PAD  4
#define HEX_NOMM 721
#define HEX_BC   96            // 32 batches * 3 channels
#define HEX_NOUT (HEX_BC * HEX_NOMM)  // 69216

__global__ __launch_bounds__(256)
void hexeye_kernel(const float* __restrict__ stim,
                   const int*   __restrict__ receptor_x,
                   const int*   __restrict__ receptor_y,
                   float*       __restrict__ out)
{
    const int gwarp = (blockIdx.x * blockDim.x + threadIdx.x) >> 5;
    const int lane  = threadIdx.x & 31;
    if (gwarp >= HEX_NOUT) return;

    const int o  = gwarp % HEX_NOMM;   // receptor id
    const int bc = gwarp / HEX_NOMM;   // batch*3 + channel

    // Clip to padded-array valid center range, as the reference does.
    int cx = receptor_x[o];
    int cy = receptor_y[o];
    cx = min(max(cx, HEX_PAD), HEX_W + HEX_PAD - 1);
    cy = min(max(cy, HEX_PAD), HEX_H + HEX_PAD - 1);

    const float* __restrict__ img =
        stim + (size_t)bc * (size_t)(HEX_H * HEX_W);

    float s = 0.0f;

    #pragma unroll
    for (int i = 0; i < 3; i++) {
        const int idx = lane + 32 * i;     // 0..95, valid < 81
        if (idx < HEX_K * HEX_K) {
            const int dy = idx / HEX_K;    // 0..8
            const int dx = idx - dy * HEX_K;
            // padded coord = c + (d - PAD); original coord m = padded - PAD
            int m = cy + dy - 2 * HEX_PAD; // range [-4, 603]
            int n = cx + dx - 2 * HEX_PAD; // range [-4, 803]
            // jnp 'reflect' (no edge duplication)
            m = (m < 0) ? -m : ((m >= HEX_H) ? (2 * HEX_H - 2 - m) : m);
            n = (n < 0) ? -n : ((n >= HEX_W) ? (2 * HEX_W - 2 - n) : n);
            s += __ldg(&img[m * HEX_W + n]);
        }
    }

    // warp tree reduction
    #pragma unroll
    for (int off = 16; off > 0; off >>= 1)
        s += __shfl_xor_sync(0xffffffffu, s, off);

    if (lane == 0)
        out[gwarp] = s * (1.0f / 81.0f);
}

extern "C" void kernel_launch(void* const* d_in, const int* in_sizes, int n_in,
                              void* d_out, int out_size)
{
    const float* stim = (const float*)d_in[0];
    const int*   rx   = (const int*)d_in[1];
    const int*   ry   = (const int*)d_in[2];
    float*       out  = (float*)d_out;

    const int warps_per_block = 256 / 32;                       // 8
    const int nblocks = (HEX_NOUT + warps_per_block - 1) / warps_per_block; // 8652

    hexeye_kernel<<<nblocks, 256>>>(stim, rx, ry, out);
}

// round 2
// speedup vs baseline: 1.4060x; 1.4060x over previous
#include <cuda_runtime.h>

// HexEye: mean over 9x9 reflect-padded patches at 721 receptor centers,
// for 32 batches x 3 channels of a 600x800 fp32 image.
//
// d_in[0]: stim        float32 [32, 3, 600, 800]
// d_in[1]: receptor_x  int32   [721]
// d_in[2]: receptor_y  int32   [721]
// d_out  : float32 [32, 3, 721]
//
// One warp per (receptor, group-of-4 bc planes). The gather indices are
// identical across all 96 bc planes, so each lane computes its reflect
// indices once and issues 4 independent loads (one per plane) -> 4x MLP,
// 1/4 the index ALU per load.

#define HEX_H     600
#define HEX_W     800
#define HEX_K     9
#define HEX_PAD   4
#define HEX_NOMM  721
#define HEX_BC    96
#define HEX_G     4                         // bc planes per warp
#define HEX_NGRP  (HEX_BC / HEX_G)          // 24
#define HEX_NWARP (HEX_NGRP * HEX_NOMM)     // 17304
#define PLANE     (HEX_H * HEX_W)

__global__ __launch_bounds__(256)
void hexeye_kernel(const float* __restrict__ stim,
                   const int*   __restrict__ receptor_x,
                   const int*   __restrict__ receptor_y,
                   float*       __restrict__ out)
{
    const int gwarp = (blockIdx.x * blockDim.x + threadIdx.x) >> 5;
    const int lane  = threadIdx.x & 31;
    if (gwarp >= HEX_NWARP) return;

    const int o   = gwarp % HEX_NOMM;   // receptor id
    const int grp = gwarp / HEX_NOMM;   // plane group (0..23)

    int cx = __ldg(&receptor_x[o]);
    int cy = __ldg(&receptor_y[o]);
    cx = min(max(cx, HEX_PAD), HEX_W + HEX_PAD - 1);
    cy = min(max(cy, HEX_PAD), HEX_H + HEX_PAD - 1);

    const float* __restrict__ img0 = stim + (size_t)(grp * HEX_G) * PLANE;

    float s0 = 0.0f, s1 = 0.0f, s2 = 0.0f, s3 = 0.0f;

    #pragma unroll
    for (int i = 0; i < 3; i++) {
        const int idx = lane + 32 * i;      // 0..95, valid < 81
        if (idx < HEX_K * HEX_K) {
            const int dy = idx / HEX_K;
            const int dx = idx - dy * HEX_K;
            int m = cy + dy - 2 * HEX_PAD;  // [-4, 603]
            int n = cx + dx - 2 * HEX_PAD;  // [-4, 803]
            // jnp 'reflect' (no edge duplication)
            m = (m < 0) ? -m : ((m >= HEX_H) ? (2 * HEX_H - 2 - m) : m);
            n = (n < 0) ? -n : ((n >= HEX_W) ? (2 * HEX_W - 2 - n) : n);
            const int off = m * HEX_W + n;
            // 4 independent loads, one per plane
            s0 += __ldg(&img0[off]);
            s1 += __ldg(&img0[off + PLANE]);
            s2 += __ldg(&img0[off + 2 * PLANE]);
            s3 += __ldg(&img0[off + 3 * PLANE]);
        }
    }

    // warp tree reductions
    #pragma unroll
    for (int off = 16; off > 0; off >>= 1) {
        s0 += __shfl_xor_sync(0xffffffffu, s0, off);
        s1 += __shfl_xor_sync(0xffffffffu, s1, off);
        s2 += __shfl_xor_sync(0xffffffffu, s2, off);
        s3 += __shfl_xor_sync(0xffffffffu, s3, off);
    }

    if (lane == 0) {
        const float inv = 1.0f / 81.0f;
        float* op = out + (size_t)(grp * HEX_G) * HEX_NOMM + o;
        op[0]            = s0 * inv;
        op[HEX_NOMM]     = s1 * inv;
        op[2 * HEX_NOMM] = s2 * inv;
        op[3 * HEX_NOMM] = s3 * inv;
    }
}

extern "C" void kernel_launch(void* const* d_in, const int* in_sizes, int n_in,
                              void* d_out, int out_size)
{
    const float* stim = (const float*)d_in[0];
    const int*   rx   = (const int*)d_in[1];
    const int*   ry   = (const int*)d_in[2];
    float*       out  = (float*)d_out;

    const int warps_per_block = 256 / 32;  // 8
    const int nblocks = (HEX_NWARP + warps_per_block - 1) / warps_per_block; // 2163

    hexeye_kernel<<<nblocks, 256>>>(stim, rx, ry, out);
}